// round 16
// baseline (speedup 1.0000x reference)
#include <cuda_runtime.h>
#include <cuda_fp16.h>
#include <math.h>
#include <stdint.h>

// ---------------------------------------------------------------------------
// Problem constants
// ---------------------------------------------------------------------------
#define S_LEN   2048
#define HIDDEN  4096
#define NHEADS  32
#define NKV     8
#define HDIM    128

// ---------------------------------------------------------------------------
// Device scratch
// ---------------------------------------------------------------------------
__device__ float g_qtmp[S_LEN * NHEADS * HDIM];
__device__ float g_ktmp[S_LEN * NKV * HDIM];
__device__ float g_vtmp[S_LEN * NKV * HDIM];
__device__ float g_cos[S_LEN * 64];
__device__ float g_sin[S_LEN * 64];

__device__ __half g_xhi[S_LEN * HIDDEN];
__device__ __half g_xlo[S_LEN * HIDDEN];
__device__ __half g_ah[S_LEN * HIDDEN];
__device__ __half g_qhi[NHEADS * S_LEN * HDIM];
__device__ __half g_qlo[NHEADS * S_LEN * HDIM];
__device__ __half g_kh[NKV * S_LEN * HDIM];
__device__ __half g_vth[NKV * HDIM * S_LEN];
__device__ __half g_wqt[HIDDEN * HIDDEN];
__device__ __half g_wkt[(NKV * HDIM) * HIDDEN];
__device__ __half g_wvt[(NKV * HDIM) * HIDDEN];
__device__ __half g_wot[HIDDEN * HIDDEN];

// ---------------------------------------------------------------------------
// Low-level helpers
// ---------------------------------------------------------------------------
__device__ __forceinline__ uint32_t smem_to_u32(const void* p) {
    uint32_t a;
    asm("{ .reg .u64 t; cvta.to.shared.u64 t, %1; cvt.u32.u64 %0, t; }"
        : "=r"(a) : "l"(p));
    return a;
}
__device__ __forceinline__ void cpasync16(uint32_t saddr, const void* g) {
    asm volatile("cp.async.cg.shared.global [%0], [%1], 16;"
                 :: "r"(saddr), "l"(g));
}
#define CP_COMMIT() asm volatile("cp.async.commit_group;" ::: "memory")
#define CP_WAIT(n)  asm volatile("cp.async.wait_group %0;" :: "n"(n) : "memory")

__device__ __forceinline__ void ldsm_x4(uint32_t addr, uint32_t r[4]) {
    asm volatile("ldmatrix.sync.aligned.m8n8.x4.shared.b16 {%0,%1,%2,%3}, [%4];"
        : "=r"(r[0]), "=r"(r[1]), "=r"(r[2]), "=r"(r[3]) : "r"(addr));
}
__device__ __forceinline__ void mma16816(float d[4], const uint32_t a[4],
                                         const uint32_t b0, const uint32_t b1) {
    asm volatile(
        "mma.sync.aligned.m16n8k16.row.col.f32.f16.f16.f32 "
        "{%0,%1,%2,%3}, {%4,%5,%6,%7}, {%8,%9}, {%0,%1,%2,%3};"
        : "+f"(d[0]), "+f"(d[1]), "+f"(d[2]), "+f"(d[3])
        : "r"(a[0]), "r"(a[1]), "r"(a[2]), "r"(a[3]), "r"(b0), "r"(b1));
}
__device__ __forceinline__ void split16(float v, __half& hi, __half& lo) {
    hi = __float2half(v);
    lo = __float2half(v - __half2float(hi));
}
__device__ __forceinline__ uint32_t packh2(__half a, __half b) {
    __half2 h; h.x = a; h.y = b;
    return *(uint32_t*)&h;
}

// ---------------------------------------------------------------------------
// Projection GEMM (QKV): 128x128 tile, BK=64, 256 threads (8 warps, 4m x 2n,
// warp tile 32x64), 2 CTAs/SM. Q/K segments: 2-term; V segment: 1-term.
// ---------------------------------------------------------------------------
#define SP3       72
#define GA_ELEMS  (128 * SP3)                 // 9216 elems per 128x64 tile
#define STG3      (3 * GA_ELEMS)              // Ahi, Alo, B
#define GEMM3_SMEM (2 * STG3 * 2)             // 110592 B -> 2 CTAs/SM
#define NCH3      (HIDDEN / 64)

__global__ __launch_bounds__(256) void gemm_mma3(
    const __half* __restrict__ Ahi, const __half* __restrict__ Alo,
    const __half* __restrict__ B0, float* __restrict__ C0, int N0,
    const __half* __restrict__ B1, float* __restrict__ C1, int N1,
    const __half* __restrict__ B2, float* __restrict__ C2, int N2,
    int seg1, int seg2) {
    extern __shared__ __align__(16) __half smbuf[];
    const int flat = blockIdx.x;
    const __half* B;
    float* C;
    int Ntot, local;
    if (flat < seg1)      { B = B0; C = C0; Ntot = N0; local = flat; }
    else if (flat < seg2) { B = B1; C = C1; Ntot = N1; local = flat - seg1; }
    else                  { B = B2; C = C2; Ntot = N2; local = flat - seg2; }
    const bool useLo = (flat < seg2);   // V segment: 1-term

    const int nx_eff = Ntot >> 7;
    const int per = 4 * nx_eff;
    const int grp = local / per, rem = local % per;
    const int m0 = (grp * 4 + (rem & 3)) * 128;
    const int n0 = (rem >> 2) * 128;

    const uint32_t sb = smem_to_u32(smbuf);
    const int tid  = threadIdx.x;
    const int lane = tid & 31;
    const int wid  = tid >> 5;                 // 0..7
    const int wm = (wid >> 1) * 32;            // 4 m-groups of 32 rows
    const int wn = (wid & 1) * 64;             // 2 n-groups of 64 cols
    const int quad = lane >> 3;
    const int wi   = lane & 7;
    const int arow = (quad & 1) * 8 + wi;
    const int acol = (quad >> 1) * 8;
    const int brow = (quad >> 1) * 8 + wi;
    const int bcol = (quad & 1) * 8;

    float acc[2][8][4];
#pragma unroll
    for (int mt = 0; mt < 2; mt++)
#pragma unroll
        for (int nt = 0; nt < 8; nt++)
#pragma unroll
            for (int q = 0; q < 4; q++) acc[mt][nt][q] = 0.f;

    auto load_stage = [&](int buf, int chunk) {
        const int k0 = chunk * 64;
        const uint32_t sbase = sb + (uint32_t)buf * STG3 * 2;
#pragma unroll
        for (int t = 0; t < 4; t++) {          // A: 128 rows x 8 chunks
            int c = tid + t * 256;             // 0..1023
            int row = c >> 3;
            int kc  = (c & 7) * 8;
            uint32_t so = sbase + (uint32_t)(row * SP3 + kc) * 2;
            size_t goA = (size_t)(m0 + row) * HIDDEN + k0 + kc;
            cpasync16(so, Ahi + goA);
            if (useLo) cpasync16(so + GA_ELEMS * 2, Alo + goA);
        }
#pragma unroll
        for (int t = 0; t < 4; t++) {          // B: 128 rows x 8 chunks
            int c = tid + t * 256;
            int row = c >> 3;
            int kc  = (c & 7) * 8;
            uint32_t so = sbase + (uint32_t)(2 * GA_ELEMS + row * SP3 + kc) * 2;
            size_t goB = (size_t)(n0 + row) * HIDDEN + k0 + kc;
            cpasync16(so, B + goB);
        }
    };

    load_stage(0, 0);
    CP_COMMIT();

    for (int chunk = 0; chunk < NCH3; chunk++) {
        CP_WAIT(0);
        __syncthreads();
        if (chunk + 1 < NCH3) {
            load_stage((chunk + 1) & 1, chunk + 1);
            CP_COMMIT();
        }
        const uint32_t stage = sb + (uint32_t)(chunk & 1) * STG3 * 2;
#pragma unroll
        for (int kk = 0; kk < 4; kk++) {
            uint32_t bF[4][4];
#pragma unroll
            for (int nt2 = 0; nt2 < 4; nt2++) {
                uint32_t bo = (uint32_t)(2 * GA_ELEMS + (wn + nt2 * 16 + brow) * SP3 +
                                         kk * 16 + bcol) * 2;
                ldsm_x4(stage + bo, bF[nt2]);
            }
#pragma unroll
            for (int mt = 0; mt < 2; mt++) {
                uint32_t aH[4], aL[4];
                uint32_t ao = (uint32_t)((wm + mt * 16 + arow) * SP3 + kk * 16 + acol) * 2;
                ldsm_x4(stage + ao, aH);
                if (useLo) ldsm_x4(stage + GA_ELEMS * 2 + ao, aL);
#pragma unroll
                for (int nt = 0; nt < 8; nt++) {
                    uint32_t b0 = bF[nt >> 1][(nt & 1) * 2];
                    uint32_t b1 = bF[nt >> 1][(nt & 1) * 2 + 1];
                    mma16816(acc[mt][nt], aH, b0, b1);
                    if (useLo) mma16816(acc[mt][nt], aL, b0, b1);
                }
            }
        }
    }

    __syncthreads();
    const int erow = lane >> 2;
    const int ecol = (lane & 3) * 2;
#pragma unroll
    for (int mt = 0; mt < 2; mt++) {
#pragma unroll
        for (int nt = 0; nt < 8; nt++) {
            int r = m0 + wm + mt * 16 + erow;
            int c = n0 + wn + nt * 8 + ecol;
            *(float2*)&C[(size_t)r * Ntot + c] =
                make_float2(acc[mt][nt][0], acc[mt][nt][1]);
            *(float2*)&C[(size_t)(r + 8) * Ntot + c] =
                make_float2(acc[mt][nt][2], acc[mt][nt][3]);
        }
    }
}

// ---------------------------------------------------------------------------
// O-projection GEMM: 128x128 tile, 256 threads, single-A fp16 (1-term MMA).
// smem 73728 B -> 3 CTAs/SM.
// ---------------------------------------------------------------------------
#define STG1      (2 * GA_ELEMS)
#define GEMM1_SMEM (2 * STG1 * 2)

__global__ __launch_bounds__(256) void gemm_mma1(
    const __half* __restrict__ A,
    const __half* __restrict__ B, float* __restrict__ C, int Ntot) {
    extern __shared__ __align__(16) __half smbuf[];
    const int local = blockIdx.x;
    const int nx_eff = Ntot >> 7;
    const int per = 4 * nx_eff;
    const int grp = local / per, rem = local % per;
    const int m0 = (grp * 4 + (rem & 3)) * 128;
    const int n0 = (rem >> 2) * 128;

    const uint32_t sb = smem_to_u32(smbuf);
    const int tid  = threadIdx.x;
    const int lane = tid & 31;
    const int wid  = tid >> 5;
    const int wm = (wid >> 1) * 32;
    const int wn = (wid & 1) * 64;
    const int quad = lane >> 3;
    const int wi   = lane & 7;
    const int arow = (quad & 1) * 8 + wi;
    const int acol = (quad >> 1) * 8;
    const int brow = (quad >> 1) * 8 + wi;
    const int bcol = (quad & 1) * 8;

    float acc[2][8][4];
#pragma unroll
    for (int mt = 0; mt < 2; mt++)
#pragma unroll
        for (int nt = 0; nt < 8; nt++)
#pragma unroll
            for (int q = 0; q < 4; q++) acc[mt][nt][q] = 0.f;

    auto load_stage = [&](int buf, int chunk) {
        const int k0 = chunk * 64;
        const uint32_t sbase = sb + (uint32_t)buf * STG1 * 2;
#pragma unroll
        for (int t = 0; t < 4; t++) {
            int c = tid + t * 256;
            int row = c >> 3;
            int kc  = (c & 7) * 8;
            cpasync16(sbase + (uint32_t)(row * SP3 + kc) * 2,
                      A + (size_t)(m0 + row) * HIDDEN + k0 + kc);
        }
#pragma unroll
        for (int t = 0; t < 4; t++) {
            int c = tid + t * 256;
            int row = c >> 3;
            int kc  = (c & 7) * 8;
            cpasync16(sbase + (uint32_t)(GA_ELEMS + row * SP3 + kc) * 2,
                      B + (size_t)(n0 + row) * HIDDEN + k0 + kc);
        }
    };

    load_stage(0, 0);
    CP_COMMIT();

    for (int chunk = 0; chunk < NCH3; chunk++) {
        CP_WAIT(0);
        __syncthreads();
        if (chunk + 1 < NCH3) {
            load_stage((chunk + 1) & 1, chunk + 1);
            CP_COMMIT();
        }
        const uint32_t stage = sb + (uint32_t)(chunk & 1) * STG1 * 2;
#pragma unroll
        for (int kk = 0; kk < 4; kk++) {
            uint32_t bF[4][4];
#pragma unroll
            for (int nt2 = 0; nt2 < 4; nt2++) {
                uint32_t bo = (uint32_t)(GA_ELEMS + (wn + nt2 * 16 + brow) * SP3 +
                                         kk * 16 + bcol) * 2;
                ldsm_x4(stage + bo, bF[nt2]);
            }
#pragma unroll
            for (int mt = 0; mt < 2; mt++) {
                uint32_t aF[4];
                uint32_t ao = (uint32_t)((wm + mt * 16 + arow) * SP3 + kk * 16 + acol) * 2;
                ldsm_x4(stage + ao, aF);
#pragma unroll
                for (int nt = 0; nt < 8; nt++)
                    mma16816(acc[mt][nt], aF,
                             bF[nt >> 1][(nt & 1) * 2],
                             bF[nt >> 1][(nt & 1) * 2 + 1]);
            }
        }
    }

    __syncthreads();
    const int erow = lane >> 2;
    const int ecol = (lane & 3) * 2;
#pragma unroll
    for (int mt = 0; mt < 2; mt++) {
#pragma unroll
        for (int nt = 0; nt < 8; nt++) {
            int r = m0 + wm + mt * 16 + erow;
            int c = n0 + wn + nt * 8 + ecol;
            *(float2*)&C[(size_t)r * Ntot + c] =
                make_float2(acc[mt][nt][0], acc[mt][nt][1]);
            *(float2*)&C[(size_t)(r + 8) * Ntot + c] =
                make_float2(acc[mt][nt][2], acc[mt][nt][3]);
        }
    }
}

// ---------------------------------------------------------------------------
// RoPE table
// ---------------------------------------------------------------------------
__global__ void rope_table(float* __restrict__ cosb, float* __restrict__ sinb) {
    const int s = blockIdx.x;
    const int d = threadIdx.x;
    float e = (float)(2 * d) * (1.0f / 128.0f);
    float invf = powf(1000000.0f, -e);
    float si, c;
    sincosf((float)s * invf, &si, &c);
    cosb[s * 64 + d] = c;
    sinb[s * 64 + d] = si;
}

// ---------------------------------------------------------------------------
// f32 -> fp16 hi/lo split, float4-vectorized
// ---------------------------------------------------------------------------
__global__ void split_kernel(const float4* __restrict__ x,
                             uint2* __restrict__ hi,
                             uint2* __restrict__ lo, int n4) {
    int i = blockIdx.x * 256 + threadIdx.x;
    if (i >= n4) return;
    float4 v = x[i];
    __half h0, l0, h1, l1, h2, l2, h3, l3;
    split16(v.x, h0, l0); split16(v.y, h1, l1);
    split16(v.z, h2, l2); split16(v.w, h3, l3);
    hi[i] = make_uint2(packh2(h0, h1), packh2(h2, h3));
    lo[i] = make_uint2(packh2(l0, l1), packh2(l2, l3));
}

// ---------------------------------------------------------------------------
// All 4 weight transposes fused
// ---------------------------------------------------------------------------
__global__ __launch_bounds__(256) void transpose_all(
    const float* __restrict__ Wq, const float* __restrict__ Wk,
    const float* __restrict__ Wv, const float* __restrict__ Wo,
    __half* __restrict__ oq, __half* __restrict__ ok,
    __half* __restrict__ ov, __half* __restrict__ oo) {
    const float* W; __half* dst; int N;
    switch (blockIdx.z) {
        case 0: W = Wq; dst = oq; N = HIDDEN; break;
        case 1: W = Wk; dst = ok; N = NKV * HDIM; break;
        case 2: W = Wv; dst = ov; N = NKV * HDIM; break;
        default: W = Wo; dst = oo; N = HIDDEN; break;
    }
    const int n0 = blockIdx.x * 32;
    if (n0 >= N) return;
    const int k0 = blockIdx.y * 32;
    __shared__ float t[32][33];
    const int tx = threadIdx.x;
    for (int r = threadIdx.y; r < 32; r += 8)
        t[r][tx] = W[(size_t)(k0 + r) * N + n0 + tx];
    __syncthreads();
    for (int r = threadIdx.y; r < 32; r += 8)
        dst[(size_t)(n0 + r) * HIDDEN + k0 + tx] = __float2half(t[tx][r]);
}

// ---------------------------------------------------------------------------
// RMSNorm + RoPE for Q (table-based; pre-scaled fp16 hi/lo splits)
// ---------------------------------------------------------------------------
__global__ __launch_bounds__(128) void norm_rope_q(
    const float* __restrict__ inp, const float* __restrict__ w,
    const float* __restrict__ cosb, const float* __restrict__ sinb,
    __half* __restrict__ qhi, __half* __restrict__ qlo) {
    const int s = blockIdx.x;
    const int h = blockIdx.y;
    const int d = threadIdx.x;

    float x = inp[((size_t)s * NHEADS + h) * HDIM + d];
    float ss = x * x;
#pragma unroll
    for (int o = 16; o; o >>= 1) ss += __shfl_xor_sync(0xffffffffu, ss, o);
    __shared__ float wss[4];
    __shared__ float xs[HDIM];
    if ((d & 31) == 0) wss[d >> 5] = ss;
    __syncthreads();
    float var = (wss[0] + wss[1] + wss[2] + wss[3]) * (1.0f / 128.0f);
    xs[d] = x * rsqrtf(var + 1e-6f) * w[d];
    __syncthreads();

    if (d < 64) {
        const float scale = 0.08838834764831845f;
        float c  = cosb[s * 64 + d];
        float si = sinb[s * 64 + d];
        float x1 = xs[d], x2 = xs[d + 64];
        float r1 = (x1 * c - x2 * si) * scale;
        float r2 = (x2 * c + x1 * si) * scale;
        size_t base = ((size_t)h * S_LEN + s) * HDIM;
        __half h1, l1, h2, l2;
        split16(r1, h1, l1);
        split16(r2, h2, l2);
        qhi[base + d] = h1; qhi[base + d + 64] = h2;
        qlo[base + d] = l1; qlo[base + d + 64] = l2;
    }
}

// ---------------------------------------------------------------------------
// RMSNorm + RoPE for K (table-based): f32 new_k + single fp16
// ---------------------------------------------------------------------------
__global__ __launch_bounds__(128) void norm_rope_k(
    const float* __restrict__ inp, const float* __restrict__ w,
    const float* __restrict__ cosb, const float* __restrict__ sinb,
    float* __restrict__ outf, __half* __restrict__ kh) {
    const int s = blockIdx.x;
    const int h = blockIdx.y;
    const int d = threadIdx.x;

    float x = inp[((size_t)s * NKV + h) * HDIM + d];
    float ss = x * x;
#pragma unroll
    for (int o = 16; o; o >>= 1) ss += __shfl_xor_sync(0xffffffffu, ss, o);
    __shared__ float wss[4];
    __shared__ float xs[HDIM];
    if ((d & 31) == 0) wss[d >> 5] = ss;
    __syncthreads();
    float var = (wss[0] + wss[1] + wss[2] + wss[3]) * (1.0f / 128.0f);
    xs[d] = x * rsqrtf(var + 1e-6f) * w[d];
    __syncthreads();

    if (d < 64) {
        float c  = cosb[s * 64 + d];
        float si = sinb[s * 64 + d];
        float x1 = xs[d], x2 = xs[d + 64];
        float r1 = x1 * c - x2 * si;
        float r2 = x2 * c + x1 * si;
        size_t base = ((size_t)h * S_LEN + s) * HDIM;
        outf[base + d]      = r1;
        outf[base + d + 64] = r2;
        kh[base + d]      = __float2half(r1);
        kh[base + d + 64] = __float2half(r2);
    }
}

// ---------------------------------------------------------------------------
// V: [s][kv*128+d] -> new_v f32 [kv][s][d] + V^T fp16 [kv][d][s]
// ---------------------------------------------------------------------------
__global__ __launch_bounds__(256) void v_split_transpose(
    const float* __restrict__ vt, float* __restrict__ outf,
    __half* __restrict__ vth) {
    __shared__ float t[32][33];
    const int kv = blockIdx.z;
    const int s0 = blockIdx.x * 32;
    const int d0 = blockIdx.y * 32;
    const int tx = threadIdx.x;
    for (int r = threadIdx.y; r < 32; r += 8) {
        float v = vt[(size_t)(s0 + r) * (NKV * HDIM) + kv * HDIM + d0 + tx];
        t[r][tx] = v;
        outf[((size_t)kv * S_LEN + s0 + r) * HDIM + d0 + tx] = v;
    }
    __syncthreads();
    for (int r = threadIdx.y; r < 32; r += 8)
        vth[((size_t)kv * HDIM + d0 + r) * S_LEN + s0 + tx] = __float2half(t[tx][r]);
}

// ---------------------------------------------------------------------------
// Tensor-core attention (round-15 max-free softmax version, unchanged)
// ---------------------------------------------------------------------------
#define AT_QP 136
#define AT_VP 72
#define S_PITCH_F 72
#define SQHI 0
#define SQLO (128 * AT_QP)
#define SSST (2 * 128 * AT_QP)
#define KSTAGE_UNITS (64 * AT_QP)
#define SSTAGE_UNITS (128 * S_PITCH_F * 2)
#define SVH  (SSST + 2 * SSTAGE_UNITS)
#define AT_SMEM_ELEMS (SVH + 128 * AT_VP)
#define AT_SMEM_BYTES (AT_SMEM_ELEMS * 2)

__global__ __launch_bounds__(256) void attention_mma(
    const __half* __restrict__ qhi, const __half* __restrict__ qlo,
    const __half* __restrict__ kh, const __half* __restrict__ vth,
    float* __restrict__ probs, __half* __restrict__ ah) {
    extern __shared__ __align__(16) __half smbuf[];
    const uint32_t sb = smem_to_u32(smbuf);
    const int h   = blockIdx.y;
    const int kvh = h >> 2;
    const int q0  = (int)(gridDim.x - 1 - blockIdx.x) * 128;
    const int tid = threadIdx.x;
    const int lane = tid & 31;
    const int wid  = tid >> 5;
    const int quad = lane >> 3, wi = lane & 7;
    const int wm   = wid * 16;
    const int arow = (quad & 1) * 8 + wi, acol = (quad >> 1) * 8;
    const int brow = (quad >> 1) * 8 + wi, bcol = (quad & 1) * 8;
    const int erow = lane >> 2, fc = (lane & 3) * 2;
    const int grow0 = q0 + wm + erow;
    const int grow1 = grow0 + 8;

    auto issue_K = [&](int jt, int buf) {
        const int c0 = jt * 64;
        const uint32_t kbase = SSST + (uint32_t)buf * KSTAGE_UNITS;
#pragma unroll
        for (int i = 0; i < 4; i++) {
            int idx = tid + i * 256;
            int row = idx >> 4, ch = idx & 15;
            size_t go = ((size_t)kvh * S_LEN + c0 + row) * HDIM + ch * 8;
            cpasync16(sb + (uint32_t)(kbase + row * AT_QP + ch * 8) * 2, kh + go);
        }
    };
    auto issue_V = [&](int jt) {
        const int c0 = jt * 64;
#pragma unroll
        for (int i = 0; i < 4; i++) {
            int idx = tid + i * 256;
            int row = idx >> 3, ch = idx & 7;
            size_t go = ((size_t)kvh * HDIM + row) * S_LEN + c0 + ch * 8;
            cpasync16(sb + (uint32_t)(SVH + row * AT_VP + ch * 8) * 2, vth + go);
        }
    };
    auto issue_S = [&](int jt, int buf) {
        const int c0 = jt * 64;
        const uint32_t sbase = (uint32_t)((SSST + buf * SSTAGE_UNITS) * 2);
#pragma unroll
        for (int i = 0; i < 8; i++) {
            int idx = tid + i * 256;
            int row = idx >> 4, ch = idx & 15;
            const float* g = &probs[((size_t)h * S_LEN + q0 + row) * S_LEN + c0 + ch * 4];
            cpasync16(sb + sbase + (uint32_t)(row * S_PITCH_F + ch * 4) * 4, g);
        }
    };
    auto compute_S = [&](int buf, float s[8][4]) {
        const uint32_t kbase = SSST + (uint32_t)buf * KSTAGE_UNITS;
#pragma unroll
        for (int nt = 0; nt < 8; nt++)
#pragma unroll
            for (int q = 0; q < 4; q++) s[nt][q] = 0.f;
#pragma unroll
        for (int term = 0; term < 2; term++) {
            const uint32_t qb = (term == 1) ? SQLO : SQHI;
#pragma unroll
            for (int kk = 0; kk < 8; kk++) {
                uint32_t a[4], b[4][4];
                ldsm_x4(sb + (uint32_t)(qb + (wm + arow) * AT_QP + kk * 16 + acol) * 2, a);
#pragma unroll
                for (int nt2 = 0; nt2 < 4; nt2++)
                    ldsm_x4(sb + (uint32_t)(kbase + (nt2 * 16 + brow) * AT_QP + kk * 16 + bcol) * 2, b[nt2]);
#pragma unroll
                for (int nt = 0; nt < 8; nt++)
                    mma16816(s[nt], a, b[nt >> 1][(nt & 1) * 2], b[nt >> 1][(nt & 1) * 2 + 1]);
            }
        }
    };

    const int jmax = (q0 + 127) >> 6;
    float l0 = 0.f, l1 = 0.f;

#pragma unroll
    for (int i = 0; i < 8; i++) {
        int idx = tid + i * 256;
        int row = idx >> 4, ch = idx & 15;
        size_t go = ((size_t)h * S_LEN + q0 + row) * HDIM + ch * 8;
        cpasync16(sb + (uint32_t)(SQHI + row * AT_QP + ch * 8) * 2, qhi + go);
        cpasync16(sb + (uint32_t)(SQLO + row * AT_QP + ch * 8) * 2, qlo + go);
    }
    issue_K(0, 0);
    CP_COMMIT();

    // ========= PASS 1: exp(scores) -> probs, row sums =========
    for (int jt = 0; jt <= jmax; jt++) {
        if (jt < jmax) {
            issue_K(jt + 1, (jt + 1) & 1);
            CP_COMMIT();
            CP_WAIT(1);
        } else {
            CP_WAIT(0);
        }
        __syncthreads();

        float s[8][4];
        compute_S(jt & 1, s);

        const int c0 = jt * 64;
        float su0 = 0.f, su1 = 0.f;
#pragma unroll
        for (int nt = 0; nt < 8; nt++) {
            int cb = c0 + nt * 8 + fc;
            float e0 = (cb     > grow0) ? 0.f : __expf(s[nt][0]);
            float e1 = (cb + 1 > grow0) ? 0.f : __expf(s[nt][1]);
            float e2 = (cb     > grow1) ? 0.f : __expf(s[nt][2]);
            float e3 = (cb + 1 > grow1) ? 0.f : __expf(s[nt][3]);
            *(float2*)&probs[((size_t)h * S_LEN + grow0) * S_LEN + cb] =
                make_float2(e0, e1);
            *(float2*)&probs[((size_t)h * S_LEN + grow1) * S_LEN + cb] =
                make_float2(e2, e3);
            su0 += e0 + e1;
            su1 += e2 + e3;
        }
        su0 += __shfl_xor_sync(0xffffffffu, su0, 1);
        su0 += __shfl_xor_sync(0xffffffffu, su0, 2);
        su1 += __shfl_xor_sync(0xffffffffu, su1, 1);
        su1 += __shfl_xor_sync(0xffffffffu, su1, 2);
        l0 += su0;
        l1 += su1;
        __syncthreads();
    }
    const float li0 = 1.0f / l0, li1 = 1.0f / l1;

    {
        float2 z = make_float2(0.f, 0.f);
        for (int jt = jmax + 1; jt < S_LEN / 64; jt++) {
            const int c0 = jt * 64;
#pragma unroll
            for (int nt = 0; nt < 8; nt++) {
                int col = c0 + nt * 8 + fc;
                *(float2*)&probs[((size_t)h * S_LEN + grow0) * S_LEN + col] = z;
                *(float2*)&probs[((size_t)h * S_LEN + grow1) * S_LEN + col] = z;
            }
        }
    }

    float o[16][4];
#pragma unroll
    for (int nt = 0; nt < 16; nt++)
#pragma unroll
        for (int q = 0; q < 4; q++) o[nt][q] = 0.f;

    issue_S(0, 0);
    CP_COMMIT();
    issue_V(0);
    CP_COMMIT();

    // ========= PASS 2: normalize (no exp), PV =========
    for (int jt = 0; jt <= jmax; jt++) {
        if (jt < jmax) {
            issue_S(jt + 1, (jt + 1) & 1);
            CP_COMMIT();
            CP_WAIT(2);
        } else {
            CP_WAIT(1);
        }
        __syncthreads();

        const float* sf = (const float*)&smbuf[SSST + (jt & 1) * SSTAGE_UNITS];
        const int c0 = jt * 64;
        const int pr0 = wm + erow, pr1 = pr0 + 8;

        uint32_t ph0[8], ph1[8], pl0[8], pl1[8];
#pragma unroll
        for (int nt = 0; nt < 8; nt++) {
            int cl = nt * 8 + fc;
            float2 e01 = *(const float2*)&sf[pr0 * S_PITCH_F + cl];
            float2 e23 = *(const float2*)&sf[pr1 * S_PITCH_F + cl];
            float p0 = e01.x * li0;
            float p1 = e01.y * li0;
            float p2 = e23.x * li1;
            float p3 = e23.y * li1;
            int cb = c0 + cl;
            *(float2*)&probs[((size_t)h * S_LEN + grow0) * S_LEN + cb] = make_float2(p0, p1);
            *(float2*)&probs[((size_t)h * S_LEN + grow1) * S_LEN + cb] = make_float2(p2, p3);
            __half h0, l0h, h1, l1h, h2, l2h, h3, l3h;
            split16(p0, h0, l0h); split16(p1, h1, l1h);
            split16(p2, h2, l2h); split16(p3, h3, l3h);
            ph0[nt] = packh2(h0, h1);
            ph1[nt] = packh2(h2, h3);
            pl0[nt] = packh2(l0h, l1h);
            pl1[nt] = packh2(l2h, l3h);
        }

        if (jt < jmax) CP_WAIT(1); else CP_WAIT(0);
        __syncthreads();

#pragma unroll
        for (int kk = 0; kk < 4; kk++) {
            uint32_t aH[4] = { ph0[2 * kk], ph1[2 * kk], ph0[2 * kk + 1], ph1[2 * kk + 1] };
            uint32_t aL[4] = { pl0[2 * kk], pl1[2 * kk], pl0[2 * kk + 1], pl1[2 * kk + 1] };
            uint32_t b[8][4];
#pragma unroll
            for (int nt2 = 0; nt2 < 8; nt2++)
                ldsm_x4(sb + (uint32_t)(SVH + (nt2 * 16 + brow) * AT_VP + kk * 16 + bcol) * 2, b[nt2]);
#pragma unroll
            for (int nt = 0; nt < 16; nt++) {
                uint32_t b0 = b[nt >> 1][(nt & 1) * 2];
                uint32_t b1 = b[nt >> 1][(nt & 1) * 2 + 1];
                mma16816(o[nt], aH, b0, b1);
                mma16816(o[nt], aL, b0, b1);
            }
        }
        __syncthreads();

        if (jt < jmax) {
            issue_V(jt + 1);
            CP_COMMIT();
        }
    }

    // ---- epilogue: single fp16 attn in [s][h*128+d] layout ----
#pragma unroll
    for (int nt = 0; nt < 16; nt++) {
        int d = nt * 8 + fc;
        size_t b0 = (size_t)grow0 * HIDDEN + h * HDIM + d;
        size_t b1 = (size_t)grow1 * HIDDEN + h * HDIM + d;
        __half2 p01; p01.x = __float2half(o[nt][0]); p01.y = __float2half(o[nt][1]);
        __half2 p23; p23.x = __float2half(o[nt][2]); p23.y = __float2half(o[nt][3]);
        *(__half2*)&ah[b0] = p01;
        *(__half2*)&ah[b1] = p23;
    }
}

// ---------------------------------------------------------------------------
// Launch
// ---------------------------------------------------------------------------
extern "C" void kernel_launch(void* const* d_in, const int* in_sizes, int n_in,
                              void* d_out, int out_size) {
    const float* X  = (const float*)d_in[0];
    const float* Wq = (const float*)d_in[2];
    const float* Wk = (const float*)d_in[3];
    const float* Wv = (const float*)d_in[4];
    const float* Wo = (const float*)d_in[5];
    const float* qw = (const float*)d_in[6];
    const float* kw = (const float*)d_in[7];

    float* out   = (float*)d_out;
    float* new_k = out + (size_t)S_LEN * HIDDEN;
    float* new_v = new_k + (size_t)NKV * S_LEN * HDIM;
    float* probs = new_v + (size_t)NKV * S_LEN * HDIM;

    float *qtmp, *ktmp, *vtmp, *cosb, *sinb;
    __half *xhi, *xlo, *ah, *qhi, *qlo, *khs, *vth;
    __half *wq, *wk, *wv, *wo;
    cudaGetSymbolAddress((void**)&qtmp, g_qtmp);
    cudaGetSymbolAddress((void**)&ktmp, g_ktmp);
    cudaGetSymbolAddress((void**)&vtmp, g_vtmp);
    cudaGetSymbolAddress((void**)&cosb, g_cos);
    cudaGetSymbolAddress((void**)&sinb, g_sin);
    cudaGetSymbolAddress((void**)&xhi, g_xhi);
    cudaGetSymbolAddress((void**)&xlo, g_xlo);
    cudaGetSymbolAddress((void**)&ah, g_ah);
    cudaGetSymbolAddress((void**)&qhi, g_qhi);
    cudaGetSymbolAddress((void**)&qlo, g_qlo);
    cudaGetSymbolAddress((void**)&khs, g_kh);
    cudaGetSymbolAddress((void**)&vth, g_vth);
    cudaGetSymbolAddress((void**)&wq, g_wqt);
    cudaGetSymbolAddress((void**)&wk, g_wkt);
    cudaGetSymbolAddress((void**)&wv, g_wvt);
    cudaGetSymbolAddress((void**)&wo, g_wot);

    // ---- conversions ----
    rope_table<<<S_LEN, 64>>>(cosb, sinb);
    transpose_all<<<dim3(128, 128, 4), dim3(32, 8)>>>(
        Wq, Wk, Wv, Wo, wq, wk, wv, wo);
    {
        int n4 = S_LEN * HIDDEN / 4;
        split_kernel<<<(n4 + 255) / 256, 256>>>(
            (const float4*)X, (uint2*)xhi, (uint2*)xlo, n4);
    }

    // ---- Q+K+V fused GEMM: 512 + 128 + 128 = 768 CTAs, 2 CTAs/SM ----
    cudaFuncSetAttribute(gemm_mma3, cudaFuncAttributeMaxDynamicSharedMemorySize,
                         GEMM3_SMEM);
    gemm_mma3<<<768, 256, GEMM3_SMEM>>>(
        xhi, xlo,
        wq, qtmp, HIDDEN,
        wk, ktmp, NKV * HDIM,
        wv, vtmp, NKV * HDIM,
        512, 640);

    // ---- RMSNorm + RoPE + splits ----
    norm_rope_q<<<dim3(S_LEN, NHEADS), 128>>>(qtmp, qw, cosb, sinb, qhi, qlo);
    norm_rope_k<<<dim3(S_LEN, NKV), 128>>>(ktmp, kw, cosb, sinb, new_k, khs);

    // ---- V transpose + fp16 ----
    v_split_transpose<<<dim3(S_LEN / 32, HDIM / 32, NKV), dim3(32, 8)>>>(
        vtmp, new_v, vth);

    // ---- attention ----
    cudaFuncSetAttribute(attention_mma,
                         cudaFuncAttributeMaxDynamicSharedMemorySize, AT_SMEM_BYTES);
    attention_mma<<<dim3(S_LEN / 128, NHEADS), 256, AT_SMEM_BYTES>>>(
        qhi, qlo, khs, vth, probs, ah);

    // ---- O projection: 512 CTAs, 3 CTAs/SM ----
    cudaFuncSetAttribute(gemm_mma1, cudaFuncAttributeMaxDynamicSharedMemorySize,
                         GEMM1_SMEM);
    gemm_mma1<<<512, 256, GEMM1_SMEM>>>(ah, wo, out, HIDDEN);
}

// round 17
// speedup vs baseline: 1.5506x; 1.5506x over previous
#include <cuda_runtime.h>
#include <cuda_fp16.h>
#include <math.h>
#include <stdint.h>

// ---------------------------------------------------------------------------
// Problem constants
// ---------------------------------------------------------------------------
#define S_LEN   2048
#define HIDDEN  4096
#define NHEADS  32
#define NKV     8
#define HDIM    128

// ---------------------------------------------------------------------------
// Device scratch
// ---------------------------------------------------------------------------
__device__ float g_qtmp[S_LEN * NHEADS * HDIM];
__device__ float g_ktmp[S_LEN * NKV * HDIM];
__device__ float g_vtmp[S_LEN * NKV * HDIM];
__device__ float g_cos[S_LEN * 64];
__device__ float g_sin[S_LEN * 64];

__device__ __half g_xhi[S_LEN * HIDDEN];
__device__ __half g_xlo[S_LEN * HIDDEN];
__device__ __half g_ah[S_LEN * HIDDEN];
__device__ __half g_qh[NHEADS * S_LEN * HDIM];   // Q single fp16, pre-scaled
__device__ __half g_kh[NKV * S_LEN * HDIM];
__device__ __half g_vth[NKV * HDIM * S_LEN];
__device__ __half g_wqt[HIDDEN * HIDDEN];
__device__ __half g_wkt[(NKV * HDIM) * HIDDEN];
__device__ __half g_wvt[(NKV * HDIM) * HIDDEN];
__device__ __half g_wot[HIDDEN * HIDDEN];

// ---------------------------------------------------------------------------
// Low-level helpers
// ---------------------------------------------------------------------------
__device__ __forceinline__ uint32_t smem_to_u32(const void* p) {
    uint32_t a;
    asm("{ .reg .u64 t; cvta.to.shared.u64 t, %1; cvt.u32.u64 %0, t; }"
        : "=r"(a) : "l"(p));
    return a;
}
__device__ __forceinline__ void cpasync16(uint32_t saddr, const void* g) {
    asm volatile("cp.async.cg.shared.global [%0], [%1], 16;"
                 :: "r"(saddr), "l"(g));
}
#define CP_COMMIT() asm volatile("cp.async.commit_group;" ::: "memory")
#define CP_WAIT(n)  asm volatile("cp.async.wait_group %0;" :: "n"(n) : "memory")

__device__ __forceinline__ void ldsm_x4(uint32_t addr, uint32_t r[4]) {
    asm volatile("ldmatrix.sync.aligned.m8n8.x4.shared.b16 {%0,%1,%2,%3}, [%4];"
        : "=r"(r[0]), "=r"(r[1]), "=r"(r[2]), "=r"(r[3]) : "r"(addr));
}
__device__ __forceinline__ void mma16816(float d[4], const uint32_t a[4],
                                         const uint32_t b0, const uint32_t b1) {
    asm volatile(
        "mma.sync.aligned.m16n8k16.row.col.f32.f16.f16.f32 "
        "{%0,%1,%2,%3}, {%4,%5,%6,%7}, {%8,%9}, {%0,%1,%2,%3};"
        : "+f"(d[0]), "+f"(d[1]), "+f"(d[2]), "+f"(d[3])
        : "r"(a[0]), "r"(a[1]), "r"(a[2]), "r"(a[3]), "r"(b0), "r"(b1));
}
__device__ __forceinline__ void split16(float v, __half& hi, __half& lo) {
    hi = __float2half(v);
    lo = __float2half(v - __half2float(hi));
}
__device__ __forceinline__ uint32_t packh2(__half a, __half b) {
    __half2 h; h.x = a; h.y = b;
    return *(uint32_t*)&h;
}

// ---------------------------------------------------------------------------
// Projection GEMM (QKV) — round-15 config: 256x128 tile, BK=64, 512 threads,
// warps 8m x 2n. Q/K segments: 2-term; V segment: 1-term.
// ---------------------------------------------------------------------------
#define SP3       72
#define A3_ELEMS  (256 * SP3)
#define B3_ELEMS  (128 * SP3)
#define STG3      (2 * A3_ELEMS + B3_ELEMS)
#define GEMM3_SMEM (2 * STG3 * 2)
#define NCH3      (HIDDEN / 64)

__global__ __launch_bounds__(512) void gemm_mma3(
    const __half* __restrict__ Ahi, const __half* __restrict__ Alo,
    const __half* __restrict__ B0, float* __restrict__ C0, int N0,
    const __half* __restrict__ B1, float* __restrict__ C1, int N1,
    const __half* __restrict__ B2, float* __restrict__ C2, int N2,
    int seg1, int seg2) {
    extern __shared__ __align__(16) __half smbuf[];
    const int flat = blockIdx.x;
    const __half* B;
    float* C;
    int Ntot, local;
    if (flat < seg1)      { B = B0; C = C0; Ntot = N0; local = flat; }
    else if (flat < seg2) { B = B1; C = C1; Ntot = N1; local = flat - seg1; }
    else                  { B = B2; C = C2; Ntot = N2; local = flat - seg2; }
    const bool useLo = (flat < seg2);   // V segment: 1-term

    const int nx_eff = Ntot >> 7;
    const int per = 4 * nx_eff;
    const int grp = local / per, rem = local % per;
    const int m0 = (grp * 4 + (rem & 3)) * 256;
    const int n0 = (rem >> 2) * 128;

    const uint32_t sb = smem_to_u32(smbuf);
    const int tid  = threadIdx.x;
    const int lane = tid & 31;
    const int wid  = tid >> 5;
    const int wm = (wid >> 1) * 32;
    const int wn = (wid & 1) * 64;
    const int quad = lane >> 3;
    const int wi   = lane & 7;
    const int arow = (quad & 1) * 8 + wi;
    const int acol = (quad >> 1) * 8;
    const int brow = (quad >> 1) * 8 + wi;
    const int bcol = (quad & 1) * 8;

    float acc[2][8][4];
#pragma unroll
    for (int mt = 0; mt < 2; mt++)
#pragma unroll
        for (int nt = 0; nt < 8; nt++)
#pragma unroll
            for (int q = 0; q < 4; q++) acc[mt][nt][q] = 0.f;

    auto load_stage = [&](int buf, int chunk) {
        const int k0 = chunk * 64;
        const uint32_t sbase = sb + (uint32_t)buf * STG3 * 2;
#pragma unroll
        for (int t = 0; t < 4; t++) {
            int c = tid + t * 512;
            int row = c >> 3;
            int kc  = (c & 7) * 8;
            uint32_t so = sbase + (uint32_t)(row * SP3 + kc) * 2;
            size_t goA = (size_t)(m0 + row) * HIDDEN + k0 + kc;
            cpasync16(so, Ahi + goA);
            if (useLo) cpasync16(so + A3_ELEMS * 2, Alo + goA);
        }
#pragma unroll
        for (int t = 0; t < 2; t++) {
            int c = tid + t * 512;
            int row = c >> 3;
            int kc  = (c & 7) * 8;
            uint32_t so = sbase + (uint32_t)(2 * A3_ELEMS + row * SP3 + kc) * 2;
            size_t goB = (size_t)(n0 + row) * HIDDEN + k0 + kc;
            cpasync16(so, B + goB);
        }
    };

    load_stage(0, 0);
    CP_COMMIT();

    for (int chunk = 0; chunk < NCH3; chunk++) {
        CP_WAIT(0);
        __syncthreads();
        if (chunk + 1 < NCH3) {
            load_stage((chunk + 1) & 1, chunk + 1);
            CP_COMMIT();
        }
        const uint32_t stage = sb + (uint32_t)(chunk & 1) * STG3 * 2;
#pragma unroll
        for (int kk = 0; kk < 4; kk++) {
            uint32_t bF[4][4];
#pragma unroll
            for (int nt2 = 0; nt2 < 4; nt2++) {
                uint32_t bo = (uint32_t)(2 * A3_ELEMS + (wn + nt2 * 16 + brow) * SP3 +
                                         kk * 16 + bcol) * 2;
                ldsm_x4(stage + bo, bF[nt2]);
            }
#pragma unroll
            for (int mt = 0; mt < 2; mt++) {
                uint32_t aH[4], aL[4];
                uint32_t ao = (uint32_t)((wm + mt * 16 + arow) * SP3 + kk * 16 + acol) * 2;
                ldsm_x4(stage + ao, aH);
                if (useLo) ldsm_x4(stage + A3_ELEMS * 2 + ao, aL);
#pragma unroll
                for (int nt = 0; nt < 8; nt++) {
                    uint32_t b0 = bF[nt >> 1][(nt & 1) * 2];
                    uint32_t b1 = bF[nt >> 1][(nt & 1) * 2 + 1];
                    mma16816(acc[mt][nt], aH, b0, b1);
                    if (useLo) mma16816(acc[mt][nt], aL, b0, b1);
                }
            }
        }
    }

    __syncthreads();
    const int erow = lane >> 2;
    const int ecol = (lane & 3) * 2;
#pragma unroll
    for (int mt = 0; mt < 2; mt++) {
#pragma unroll
        for (int nt = 0; nt < 8; nt++) {
            int r = m0 + wm + mt * 16 + erow;
            int c = n0 + wn + nt * 8 + ecol;
            *(float2*)&C[(size_t)r * Ntot + c] =
                make_float2(acc[mt][nt][0], acc[mt][nt][1]);
            *(float2*)&C[(size_t)(r + 8) * Ntot + c] =
                make_float2(acc[mt][nt][2], acc[mt][nt][3]);
        }
    }
}

// ---------------------------------------------------------------------------
// O-projection GEMM — round-15 config: 256x128, 512 threads, 1-term.
// ---------------------------------------------------------------------------
#define STG1      (A3_ELEMS + B3_ELEMS)
#define GEMM1_SMEM (2 * STG1 * 2)

__global__ __launch_bounds__(512) void gemm_mma1(
    const __half* __restrict__ A,
    const __half* __restrict__ B, float* __restrict__ C, int Ntot) {
    extern __shared__ __align__(16) __half smbuf[];
    const int local = blockIdx.x;
    const int nx_eff = Ntot >> 7;
    const int per = 4 * nx_eff;
    const int grp = local / per, rem = local % per;
    const int m0 = (grp * 4 + (rem & 3)) * 256;
    const int n0 = (rem >> 2) * 128;

    const uint32_t sb = smem_to_u32(smbuf);
    const int tid  = threadIdx.x;
    const int lane = tid & 31;
    const int wid  = tid >> 5;
    const int wm = (wid >> 1) * 32;
    const int wn = (wid & 1) * 64;
    const int quad = lane >> 3;
    const int wi   = lane & 7;
    const int arow = (quad & 1) * 8 + wi;
    const int acol = (quad >> 1) * 8;
    const int brow = (quad >> 1) * 8 + wi;
    const int bcol = (quad & 1) * 8;

    float acc[2][8][4];
#pragma unroll
    for (int mt = 0; mt < 2; mt++)
#pragma unroll
        for (int nt = 0; nt < 8; nt++)
#pragma unroll
            for (int q = 0; q < 4; q++) acc[mt][nt][q] = 0.f;

    auto load_stage = [&](int buf, int chunk) {
        const int k0 = chunk * 64;
        const uint32_t sbase = sb + (uint32_t)buf * STG1 * 2;
#pragma unroll
        for (int t = 0; t < 4; t++) {
            int c = tid + t * 512;
            int row = c >> 3;
            int kc  = (c & 7) * 8;
            cpasync16(sbase + (uint32_t)(row * SP3 + kc) * 2,
                      A + (size_t)(m0 + row) * HIDDEN + k0 + kc);
        }
#pragma unroll
        for (int t = 0; t < 2; t++) {
            int c = tid + t * 512;
            int row = c >> 3;
            int kc  = (c & 7) * 8;
            cpasync16(sbase + (uint32_t)(A3_ELEMS + row * SP3 + kc) * 2,
                      B + (size_t)(n0 + row) * HIDDEN + k0 + kc);
        }
    };

    load_stage(0, 0);
    CP_COMMIT();

    for (int chunk = 0; chunk < NCH3; chunk++) {
        CP_WAIT(0);
        __syncthreads();
        if (chunk + 1 < NCH3) {
            load_stage((chunk + 1) & 1, chunk + 1);
            CP_COMMIT();
        }
        const uint32_t stage = sb + (uint32_t)(chunk & 1) * STG1 * 2;
#pragma unroll
        for (int kk = 0; kk < 4; kk++) {
            uint32_t bF[4][4];
#pragma unroll
            for (int nt2 = 0; nt2 < 4; nt2++) {
                uint32_t bo = (uint32_t)(A3_ELEMS + (wn + nt2 * 16 + brow) * SP3 +
                                         kk * 16 + bcol) * 2;
                ldsm_x4(stage + bo, bF[nt2]);
            }
#pragma unroll
            for (int mt = 0; mt < 2; mt++) {
                uint32_t aF[4];
                uint32_t ao = (uint32_t)((wm + mt * 16 + arow) * SP3 + kk * 16 + acol) * 2;
                ldsm_x4(stage + ao, aF);
#pragma unroll
                for (int nt = 0; nt < 8; nt++)
                    mma16816(acc[mt][nt], aF,
                             bF[nt >> 1][(nt & 1) * 2],
                             bF[nt >> 1][(nt & 1) * 2 + 1]);
            }
        }
    }

    __syncthreads();
    const int erow = lane >> 2;
    const int ecol = (lane & 3) * 2;
#pragma unroll
    for (int mt = 0; mt < 2; mt++) {
#pragma unroll
        for (int nt = 0; nt < 8; nt++) {
            int r = m0 + wm + mt * 16 + erow;
            int c = n0 + wn + nt * 8 + ecol;
            *(float2*)&C[(size_t)r * Ntot + c] =
                make_float2(acc[mt][nt][0], acc[mt][nt][1]);
            *(float2*)&C[(size_t)(r + 8) * Ntot + c] =
                make_float2(acc[mt][nt][2], acc[mt][nt][3]);
        }
    }
}

// ---------------------------------------------------------------------------
// RoPE table
// ---------------------------------------------------------------------------
__global__ void rope_table(float* __restrict__ cosb, float* __restrict__ sinb) {
    const int s = blockIdx.x;
    const int d = threadIdx.x;
    float e = (float)(2 * d) * (1.0f / 128.0f);
    float invf = powf(1000000.0f, -e);
    float si, c;
    sincosf((float)s * invf, &si, &c);
    cosb[s * 64 + d] = c;
    sinb[s * 64 + d] = si;
}

// ---------------------------------------------------------------------------
// f32 -> fp16 hi/lo split, float4-vectorized
// ---------------------------------------------------------------------------
__global__ void split_kernel(const float4* __restrict__ x,
                             uint2* __restrict__ hi,
                             uint2* __restrict__ lo, int n4) {
    int i = blockIdx.x * 256 + threadIdx.x;
    if (i >= n4) return;
    float4 v = x[i];
    __half h0, l0, h1, l1, h2, l2, h3, l3;
    split16(v.x, h0, l0); split16(v.y, h1, l1);
    split16(v.z, h2, l2); split16(v.w, h3, l3);
    hi[i] = make_uint2(packh2(h0, h1), packh2(h2, h3));
    lo[i] = make_uint2(packh2(l0, l1), packh2(l2, l3));
}

// ---------------------------------------------------------------------------
// All 4 weight transposes fused
// ---------------------------------------------------------------------------
__global__ __launch_bounds__(256) void transpose_all(
    const float* __restrict__ Wq, const float* __restrict__ Wk,
    const float* __restrict__ Wv, const float* __restrict__ Wo,
    __half* __restrict__ oq, __half* __restrict__ ok,
    __half* __restrict__ ov, __half* __restrict__ oo) {
    const float* W; __half* dst; int N;
    switch (blockIdx.z) {
        case 0: W = Wq; dst = oq; N = HIDDEN; break;
        case 1: W = Wk; dst = ok; N = NKV * HDIM; break;
        case 2: W = Wv; dst = ov; N = NKV * HDIM; break;
        default: W = Wo; dst = oo; N = HIDDEN; break;
    }
    const int n0 = blockIdx.x * 32;
    if (n0 >= N) return;
    const int k0 = blockIdx.y * 32;
    __shared__ float t[32][33];
    const int tx = threadIdx.x;
    for (int r = threadIdx.y; r < 32; r += 8)
        t[r][tx] = W[(size_t)(k0 + r) * N + n0 + tx];
    __syncthreads();
    for (int r = threadIdx.y; r < 32; r += 8)
        dst[(size_t)(n0 + r) * HIDDEN + k0 + tx] = __float2half(t[tx][r]);
}

// ---------------------------------------------------------------------------
// RMSNorm + RoPE for Q: single fp16 (unsplit), pre-scaled
// ---------------------------------------------------------------------------
__global__ __launch_bounds__(128) void norm_rope_q(
    const float* __restrict__ inp, const float* __restrict__ w,
    const float* __restrict__ cosb, const float* __restrict__ sinb,
    __half* __restrict__ qh) {
    const int s = blockIdx.x;
    const int h = blockIdx.y;
    const int d = threadIdx.x;

    float x = inp[((size_t)s * NHEADS + h) * HDIM + d];
    float ss = x * x;
#pragma unroll
    for (int o = 16; o; o >>= 1) ss += __shfl_xor_sync(0xffffffffu, ss, o);
    __shared__ float wss[4];
    __shared__ float xs[HDIM];
    if ((d & 31) == 0) wss[d >> 5] = ss;
    __syncthreads();
    float var = (wss[0] + wss[1] + wss[2] + wss[3]) * (1.0f / 128.0f);
    xs[d] = x * rsqrtf(var + 1e-6f) * w[d];
    __syncthreads();

    if (d < 64) {
        const float scale = 0.08838834764831845f;
        float c  = cosb[s * 64 + d];
        float si = sinb[s * 64 + d];
        float x1 = xs[d], x2 = xs[d + 64];
        float r1 = (x1 * c - x2 * si) * scale;
        float r2 = (x2 * c + x1 * si) * scale;
        size_t base = ((size_t)h * S_LEN + s) * HDIM;
        qh[base + d]      = __float2half(r1);
        qh[base + d + 64] = __float2half(r2);
    }
}

// ---------------------------------------------------------------------------
// RMSNorm + RoPE for K: f32 new_k + single fp16
// ---------------------------------------------------------------------------
__global__ __launch_bounds__(128) void norm_rope_k(
    const float* __restrict__ inp, const float* __restrict__ w,
    const float* __restrict__ cosb, const float* __restrict__ sinb,
    float* __restrict__ outf, __half* __restrict__ kh) {
    const int s = blockIdx.x;
    const int h = blockIdx.y;
    const int d = threadIdx.x;

    float x = inp[((size_t)s * NKV + h) * HDIM + d];
    float ss = x * x;
#pragma unroll
    for (int o = 16; o; o >>= 1) ss += __shfl_xor_sync(0xffffffffu, ss, o);
    __shared__ float wss[4];
    __shared__ float xs[HDIM];
    if ((d & 31) == 0) wss[d >> 5] = ss;
    __syncthreads();
    float var = (wss[0] + wss[1] + wss[2] + wss[3]) * (1.0f / 128.0f);
    xs[d] = x * rsqrtf(var + 1e-6f) * w[d];
    __syncthreads();

    if (d < 64) {
        float c  = cosb[s * 64 + d];
        float si = sinb[s * 64 + d];
        float x1 = xs[d], x2 = xs[d + 64];
        float r1 = x1 * c - x2 * si;
        float r2 = x2 * c + x1 * si;
        size_t base = ((size_t)h * S_LEN + s) * HDIM;
        outf[base + d]      = r1;
        outf[base + d + 64] = r2;
        kh[base + d]      = __float2half(r1);
        kh[base + d + 64] = __float2half(r2);
    }
}

// ---------------------------------------------------------------------------
// V: [s][kv*128+d] -> new_v f32 [kv][s][d] + V^T fp16 [kv][d][s]
// ---------------------------------------------------------------------------
__global__ __launch_bounds__(256) void v_split_transpose(
    const float* __restrict__ vt, float* __restrict__ outf,
    __half* __restrict__ vth) {
    __shared__ float t[32][33];
    const int kv = blockIdx.z;
    const int s0 = blockIdx.x * 32;
    const int d0 = blockIdx.y * 32;
    const int tx = threadIdx.x;
    for (int r = threadIdx.y; r < 32; r += 8) {
        float v = vt[(size_t)(s0 + r) * (NKV * HDIM) + kv * HDIM + d0 + tx];
        t[r][tx] = v;
        outf[((size_t)kv * S_LEN + s0 + r) * HDIM + d0 + tx] = v;
    }
    __syncthreads();
    for (int r = threadIdx.y; r < 32; r += 8)
        vth[((size_t)kv * HDIM + d0 + r) * S_LEN + s0 + tx] = __float2half(t[tx][r]);
}

// ---------------------------------------------------------------------------
// Tensor-core attention (max-free softmax; Q single fp16, 1-term QK^T):
//  Pass 1: QK^T (1-term), mask, write exp(s) to probs, row-sum only.
//  Pass 2: stream exp(s) back, p = e*(1/l), rewrite probs, P split in regs,
//          PV (2-term).
// ---------------------------------------------------------------------------
#define AT_QP 136
#define AT_VP 72
#define S_PITCH_F 72
#define SQ 0
#define SSST (128 * AT_QP)                    // 17408: K stages / S stages
#define KSTAGE_UNITS (64 * AT_QP)             // 8704
#define SSTAGE_UNITS (128 * S_PITCH_F * 2)    // 18432
#define SVH  (SSST + 2 * SSTAGE_UNITS)        // 54272
#define AT_SMEM_ELEMS (SVH + 128 * AT_VP)     // 63488
#define AT_SMEM_BYTES (AT_SMEM_ELEMS * 2)     // 126976

__global__ __launch_bounds__(256) void attention_mma(
    const __half* __restrict__ qh,
    const __half* __restrict__ kh, const __half* __restrict__ vth,
    float* __restrict__ probs, __half* __restrict__ ah) {
    extern __shared__ __align__(16) __half smbuf[];
    const uint32_t sb = smem_to_u32(smbuf);
    const int h   = blockIdx.y;
    const int kvh = h >> 2;
    const int q0  = (int)(gridDim.x - 1 - blockIdx.x) * 128;
    const int tid = threadIdx.x;
    const int lane = tid & 31;
    const int wid  = tid >> 5;
    const int quad = lane >> 3, wi = lane & 7;
    const int wm   = wid * 16;
    const int arow = (quad & 1) * 8 + wi, acol = (quad >> 1) * 8;
    const int brow = (quad >> 1) * 8 + wi, bcol = (quad & 1) * 8;
    const int erow = lane >> 2, fc = (lane & 3) * 2;
    const int grow0 = q0 + wm + erow;
    const int grow1 = grow0 + 8;

    auto issue_K = [&](int jt, int buf) {
        const int c0 = jt * 64;
        const uint32_t kbase = SSST + (uint32_t)buf * KSTAGE_UNITS;
#pragma unroll
        for (int i = 0; i < 4; i++) {
            int idx = tid + i * 256;
            int row = idx >> 4, ch = idx & 15;
            size_t go = ((size_t)kvh * S_LEN + c0 + row) * HDIM + ch * 8;
            cpasync16(sb + (uint32_t)(kbase + row * AT_QP + ch * 8) * 2, kh + go);
        }
    };
    auto issue_V = [&](int jt) {
        const int c0 = jt * 64;
#pragma unroll
        for (int i = 0; i < 4; i++) {
            int idx = tid + i * 256;
            int row = idx >> 3, ch = idx & 7;
            size_t go = ((size_t)kvh * HDIM + row) * S_LEN + c0 + ch * 8;
            cpasync16(sb + (uint32_t)(SVH + row * AT_VP + ch * 8) * 2, vth + go);
        }
    };
    auto issue_S = [&](int jt, int buf) {
        const int c0 = jt * 64;
        const uint32_t sbase = (uint32_t)((SSST + buf * SSTAGE_UNITS) * 2);
#pragma unroll
        for (int i = 0; i < 8; i++) {
            int idx = tid + i * 256;
            int row = idx >> 4, ch = idx & 15;
            const float* g = &probs[((size_t)h * S_LEN + q0 + row) * S_LEN + c0 + ch * 4];
            cpasync16(sb + sbase + (uint32_t)(row * S_PITCH_F + ch * 4) * 4, g);
        }
    };
    auto compute_S = [&](int buf, float s[8][4]) {
        const uint32_t kbase = SSST + (uint32_t)buf * KSTAGE_UNITS;
#pragma unroll
        for (int nt = 0; nt < 8; nt++)
#pragma unroll
            for (int q = 0; q < 4; q++) s[nt][q] = 0.f;
#pragma unroll
        for (int kk = 0; kk < 8; kk++) {
            uint32_t a[4], b[4][4];
            ldsm_x4(sb + (uint32_t)(SQ + (wm + arow) * AT_QP + kk * 16 + acol) * 2, a);
#pragma unroll
            for (int nt2 = 0; nt2 < 4; nt2++)
                ldsm_x4(sb + (uint32_t)(kbase + (nt2 * 16 + brow) * AT_QP + kk * 16 + bcol) * 2, b[nt2]);
#pragma unroll
            for (int nt = 0; nt < 8; nt++)
                mma16816(s[nt], a, b[nt >> 1][(nt & 1) * 2], b[nt >> 1][(nt & 1) * 2 + 1]);
        }
    };

    const int jmax = (q0 + 127) >> 6;
    float l0 = 0.f, l1 = 0.f;

    // ---- prologue pass 1: Q single + K(0) ----
#pragma unroll
    for (int i = 0; i < 8; i++) {
        int idx = tid + i * 256;
        int row = idx >> 4, ch = idx & 15;
        size_t go = ((size_t)h * S_LEN + q0 + row) * HDIM + ch * 8;
        cpasync16(sb + (uint32_t)(SQ + row * AT_QP + ch * 8) * 2, qh + go);
    }
    issue_K(0, 0);
    CP_COMMIT();

    // ========= PASS 1: exp(scores) -> probs, row sums =========
    for (int jt = 0; jt <= jmax; jt++) {
        if (jt < jmax) {
            issue_K(jt + 1, (jt + 1) & 1);
            CP_COMMIT();
            CP_WAIT(1);
        } else {
            CP_WAIT(0);
        }
        __syncthreads();

        float s[8][4];
        compute_S(jt & 1, s);

        const int c0 = jt * 64;
        float su0 = 0.f, su1 = 0.f;
#pragma unroll
        for (int nt = 0; nt < 8; nt++) {
            int cb = c0 + nt * 8 + fc;
            float e0 = (cb     > grow0) ? 0.f : __expf(s[nt][0]);
            float e1 = (cb + 1 > grow0) ? 0.f : __expf(s[nt][1]);
            float e2 = (cb     > grow1) ? 0.f : __expf(s[nt][2]);
            float e3 = (cb + 1 > grow1) ? 0.f : __expf(s[nt][3]);
            *(float2*)&probs[((size_t)h * S_LEN + grow0) * S_LEN + cb] =
                make_float2(e0, e1);
            *(float2*)&probs[((size_t)h * S_LEN + grow1) * S_LEN + cb] =
                make_float2(e2, e3);
            su0 += e0 + e1;
            su1 += e2 + e3;
        }
        su0 += __shfl_xor_sync(0xffffffffu, su0, 1);
        su0 += __shfl_xor_sync(0xffffffffu, su0, 2);
        su1 += __shfl_xor_sync(0xffffffffu, su1, 1);
        su1 += __shfl_xor_sync(0xffffffffu, su1, 2);
        l0 += su0;
        l1 += su1;
        __syncthreads();
    }
    const float li0 = 1.0f / l0, li1 = 1.0f / l1;

    // ---- zero-fill masked probs tiles ----
    {
        float2 z = make_float2(0.f, 0.f);
        for (int jt = jmax + 1; jt < S_LEN / 64; jt++) {
            const int c0 = jt * 64;
#pragma unroll
            for (int nt = 0; nt < 8; nt++) {
                int col = c0 + nt * 8 + fc;
                *(float2*)&probs[((size_t)h * S_LEN + grow0) * S_LEN + col] = z;
                *(float2*)&probs[((size_t)h * S_LEN + grow1) * S_LEN + col] = z;
            }
        }
    }

    float o[16][4];
#pragma unroll
    for (int nt = 0; nt < 16; nt++)
#pragma unroll
        for (int q = 0; q < 4; q++) o[nt][q] = 0.f;

    issue_S(0, 0);
    CP_COMMIT();
    issue_V(0);
    CP_COMMIT();

    // ========= PASS 2: normalize (no exp), PV (2-term) =========
    for (int jt = 0; jt <= jmax; jt++) {
        if (jt < jmax) {
            issue_S(jt + 1, (jt + 1) & 1);
            CP_COMMIT();
            CP_WAIT(2);
        } else {
            CP_WAIT(1);
        }
        __syncthreads();

        const float* sf = (const float*)&smbuf[SSST + (jt & 1) * SSTAGE_UNITS];
        const int c0 = jt * 64;
        const int pr0 = wm + erow, pr1 = pr0 + 8;

        uint32_t ph0[8], ph1[8], pl0[8], pl1[8];
#pragma unroll
        for (int nt = 0; nt < 8; nt++) {
            int cl = nt * 8 + fc;
            float2 e01 = *(const float2*)&sf[pr0 * S_PITCH_F + cl];
            float2 e23 = *(const float2*)&sf[pr1 * S_PITCH_F + cl];
            float p0 = e01.x * li0;
            float p1 = e01.y * li0;
            float p2 = e23.x * li1;
            float p3 = e23.y * li1;
            int cb = c0 + cl;
            *(float2*)&probs[((size_t)h * S_LEN + grow0) * S_LEN + cb] = make_float2(p0, p1);
            *(float2*)&probs[((size_t)h * S_LEN + grow1) * S_LEN + cb] = make_float2(p2, p3);
            __half h0, l0h, h1, l1h, h2, l2h, h3, l3h;
            split16(p0, h0, l0h); split16(p1, h1, l1h);
            split16(p2, h2, l2h); split16(p3, h3, l3h);
            ph0[nt] = packh2(h0, h1);
            ph1[nt] = packh2(h2, h3);
            pl0[nt] = packh2(l0h, l1h);
            pl1[nt] = packh2(l2h, l3h);
        }

        if (jt < jmax) CP_WAIT(1); else CP_WAIT(0);
        __syncthreads();

#pragma unroll
        for (int kk = 0; kk < 4; kk++) {
            uint32_t aH[4] = { ph0[2 * kk], ph1[2 * kk], ph0[2 * kk + 1], ph1[2 * kk + 1] };
            uint32_t aL[4] = { pl0[2 * kk], pl1[2 * kk], pl0[2 * kk + 1], pl1[2 * kk + 1] };
            uint32_t b[8][4];
#pragma unroll
            for (int nt2 = 0; nt2 < 8; nt2++)
                ldsm_x4(sb + (uint32_t)(SVH + (nt2 * 16 + brow) * AT_VP + kk * 16 + bcol) * 2, b[nt2]);
#pragma unroll
            for (int nt = 0; nt < 16; nt++) {
                uint32_t b0 = b[nt >> 1][(nt & 1) * 2];
                uint32_t b1 = b[nt >> 1][(nt & 1) * 2 + 1];
                mma16816(o[nt], aH, b0, b1);
                mma16816(o[nt], aL, b0, b1);
            }
        }
        __syncthreads();

        if (jt < jmax) {
            issue_V(jt + 1);
            CP_COMMIT();
        }
    }

    // ---- epilogue: single fp16 attn in [s][h*128+d] layout ----
#pragma unroll
    for (int nt = 0; nt < 16; nt++) {
        int d = nt * 8 + fc;
        size_t b0 = (size_t)grow0 * HIDDEN + h * HDIM + d;
        size_t b1 = (size_t)grow1 * HIDDEN + h * HDIM + d;
        __half2 p01; p01.x = __float2half(o[nt][0]); p01.y = __float2half(o[nt][1]);
        __half2 p23; p23.x = __float2half(o[nt][2]); p23.y = __float2half(o[nt][3]);
        *(__half2*)&ah[b0] = p01;
        *(__half2*)&ah[b1] = p23;
    }
}

// ---------------------------------------------------------------------------
// Launch
// ---------------------------------------------------------------------------
extern "C" void kernel_launch(void* const* d_in, const int* in_sizes, int n_in,
                              void* d_out, int out_size) {
    const float* X  = (const float*)d_in[0];
    const float* Wq = (const float*)d_in[2];
    const float* Wk = (const float*)d_in[3];
    const float* Wv = (const float*)d_in[4];
    const float* Wo = (const float*)d_in[5];
    const float* qw = (const float*)d_in[6];
    const float* kw = (const float*)d_in[7];

    float* out   = (float*)d_out;
    float* new_k = out + (size_t)S_LEN * HIDDEN;
    float* new_v = new_k + (size_t)NKV * S_LEN * HDIM;
    float* probs = new_v + (size_t)NKV * S_LEN * HDIM;

    float *qtmp, *ktmp, *vtmp, *cosb, *sinb;
    __half *xhi, *xlo, *ah, *qh, *khs, *vth;
    __half *wq, *wk, *wv, *wo;
    cudaGetSymbolAddress((void**)&qtmp, g_qtmp);
    cudaGetSymbolAddress((void**)&ktmp, g_ktmp);
    cudaGetSymbolAddress((void**)&vtmp, g_vtmp);
    cudaGetSymbolAddress((void**)&cosb, g_cos);
    cudaGetSymbolAddress((void**)&sinb, g_sin);
    cudaGetSymbolAddress((void**)&xhi, g_xhi);
    cudaGetSymbolAddress((void**)&xlo, g_xlo);
    cudaGetSymbolAddress((void**)&ah, g_ah);
    cudaGetSymbolAddress((void**)&qh, g_qh);
    cudaGetSymbolAddress((void**)&khs, g_kh);
    cudaGetSymbolAddress((void**)&vth, g_vth);
    cudaGetSymbolAddress((void**)&wq, g_wqt);
    cudaGetSymbolAddress((void**)&wk, g_wkt);
    cudaGetSymbolAddress((void**)&wv, g_wvt);
    cudaGetSymbolAddress((void**)&wo, g_wot);

    // ---- conversions ----
    rope_table<<<S_LEN, 64>>>(cosb, sinb);
    transpose_all<<<dim3(128, 128, 4), dim3(32, 8)>>>(
        Wq, Wk, Wv, Wo, wq, wk, wv, wo);
    {
        int n4 = S_LEN * HIDDEN / 4;
        split_kernel<<<(n4 + 255) / 256, 256>>>(
            (const float4*)X, (uint2*)xhi, (uint2*)xlo, n4);
    }

    // ---- Q+K+V fused GEMM (round-15 shape): 256+64+64 = 384 CTAs ----
    cudaFuncSetAttribute(gemm_mma3, cudaFuncAttributeMaxDynamicSharedMemorySize,
                         GEMM3_SMEM);
    gemm_mma3<<<384, 512, GEMM3_SMEM>>>(
        xhi, xlo,
        wq, qtmp, HIDDEN,
        wk, ktmp, NKV * HDIM,
        wv, vtmp, NKV * HDIM,
        256, 320);

    // ---- RMSNorm + RoPE ----
    norm_rope_q<<<dim3(S_LEN, NHEADS), 128>>>(qtmp, qw, cosb, sinb, qh);
    norm_rope_k<<<dim3(S_LEN, NKV), 128>>>(ktmp, kw, cosb, sinb, new_k, khs);

    // ---- V transpose + fp16 ----
    v_split_transpose<<<dim3(S_LEN / 32, HDIM / 32, NKV), dim3(32, 8)>>>(
        vtmp, new_v, vth);

    // ---- attention (Q 1-term) ----
    cudaFuncSetAttribute(attention_mma,
                         cudaFuncAttributeMaxDynamicSharedMemorySize, AT_SMEM_BYTES);
    attention_mma<<<dim3(S_LEN / 128, NHEADS), 256, AT_SMEM_BYTES>>>(
        qh, khs, vth, probs, ah);

    // ---- O projection (round-15 shape): 256 CTAs ----
    cudaFuncSetAttribute(gemm_mma1, cudaFuncAttributeMaxDynamicSharedMemorySize,
                         GEMM1_SMEM);
    gemm_mma1<<<256, 512, GEMM1_SMEM>>>(ah, wo, out, HIDDEN);
}